// round 6
// baseline (speedup 1.0000x reference)
#include <cuda_runtime.h>
#include <cuda_bf16.h>
#include <math.h>
#include <stdint.h>

// Problem constants
#define BATCH 2
#define SEQ   2048
#define CDIM  1024
#define NHEAD 16
#define HDIM  64
#define C3    (3*CDIM)          // 3072
#define MROWS (BATCH*SEQ)       // 4096

// Scratch (no cudaMalloc allowed)
__device__ float g_qkv[(size_t)MROWS * C3];       // [B,T,3,H,D] (tf32-rounded)
__device__ float g_attn[(size_t)MROWS * CDIM];    // [B,T,C]     (tf32-rounded)
__device__ float g_xr[(size_t)MROWS * CDIM];      // x, tf32-rounded
__device__ float g_wqkvr[(size_t)CDIM * C3];      // Wqkv, tf32-rounded
__device__ float g_woutr[(size_t)CDIM * CDIM];    // Wout, tf32-rounded

__device__ __forceinline__ uint32_t f2tf32(float f) {
    uint32_t r;
    asm("cvt.rna.tf32.f32 %0, %1;" : "=r"(r) : "f"(f));
    return r;
}
__device__ __forceinline__ float fexp2(float x) {
    float y;
    asm("ex2.approx.f32 %0, %1;" : "=f"(y) : "f"(x));
    return y;
}
__device__ __forceinline__ uint32_t smem_u32(const void* p) {
    uint32_t a;
    asm("{ .reg .u64 t; cvta.to.shared.u64 t, %1; cvt.u32.u64 %0, t; }" : "=r"(a) : "l"(p));
    return a;
}
#define CP_ASYNC16(dst_u32, src_ptr) \
    asm volatile("cp.async.cg.shared.global [%0], [%1], 16;" :: "r"(dst_u32), "l"(src_ptr) : "memory")
#define CP_COMMIT() asm volatile("cp.async.commit_group;" ::: "memory")
#define CP_WAIT0()  asm volatile("cp.async.wait_group 0;" ::: "memory")
#define CP_WAIT1()  asm volatile("cp.async.wait_group 1;" ::: "memory")

__device__ __forceinline__ void mma_tf32(float c[4], const uint32_t a[4], const uint32_t b[2]) {
    asm volatile(
        "mma.sync.aligned.m16n8k8.row.col.f32.tf32.tf32.f32 "
        "{%0,%1,%2,%3}, {%4,%5,%6,%7}, {%8,%9}, {%0,%1,%2,%3};"
        : "+f"(c[0]), "+f"(c[1]), "+f"(c[2]), "+f"(c[3])
        : "r"(a[0]), "r"(a[1]), "r"(a[2]), "r"(a[3]), "r"(b[0]), "r"(b[1]));
}

// ---------------------------------------------------------------------------
// tf32 pre-round pass (memory-bound)
// ---------------------------------------------------------------------------
__global__ __launch_bounds__(256)
void round_tf32_kernel(const float* __restrict__ in, float* __restrict__ out, int n4)
{
    int i = blockIdx.x * blockDim.x + threadIdx.x;
    if (i < n4) {
        float4 v = ((const float4*)in)[i];
        float4 o;
        o.x = __uint_as_float(f2tf32(v.x));
        o.y = __uint_as_float(f2tf32(v.y));
        o.z = __uint_as_float(f2tf32(v.z));
        o.w = __uint_as_float(f2tf32(v.w));
        ((float4*)out)[i] = o;
    }
}

// ---------------------------------------------------------------------------
// tf32 mma.sync GEMM + bias, cp.async 2-stage ring, 2 CTAs/SM.
// C[M,N] = A[M,K] @ B[K,N] + bias[N]. A,B must be tf32-pre-rounded.
// CTA 128x128, BK=32, 8 warps (2x4), warp tile 64x32.
// ---------------------------------------------------------------------------
#define GBM 128
#define GBN 128
#define GBK 32
#define A_STRIDE 36
#define B_STRIDE 136
#define A_FLOATS (GBM * A_STRIDE)       // 4608
#define B_FLOATS (GBK * B_STRIDE)       // 4352
#define STG_FLOATS (A_FLOATS + B_FLOATS)
#define GEMM_SMEM (2 * STG_FLOATS * 4)  // 71680 B -> 2 CTAs/SM

template<bool RND>
__global__ __launch_bounds__(256, 2)
void gemm_tc_kernel(const float* __restrict__ A,
                    const float* __restrict__ B,
                    const float* __restrict__ bias,
                    float* __restrict__ C,
                    int M, int N, int K)
{
    extern __shared__ float smem[];
    const int tid = threadIdx.x;
    const int wid = tid >> 5;
    const int l   = tid & 31;
    const int warpM = wid >> 2;
    const int warpN = wid & 3;
    const int rowbase = blockIdx.y * GBM;
    const int colbase = blockIdx.x * GBN;

    const uint32_t smb = smem_u32(smem);

    float acc[4][4][4];
    #pragma unroll
    for (int i = 0; i < 4; i++)
        #pragma unroll
        for (int j = 0; j < 4; j++)
            #pragma unroll
            for (int q = 0; q < 4; q++) acc[i][j][q] = 0.f;

    const int a_r = tid >> 3, a_c = (tid & 7) * 4;
    const int b_r = tid >> 5, b_c = (tid & 31) * 4;

    const int S = K / GBK;

    auto load_stage = [&](int stg, int k0) {
        const uint32_t sa = smb + stg * STG_FLOATS * 4;
        const uint32_t sb = sa + A_FLOATS * 4;
        #pragma unroll
        for (int it = 0; it < 4; it++) {
            const int r = it * 32 + a_r;
            CP_ASYNC16(sa + (uint32_t)(r * A_STRIDE + a_c) * 4,
                       A + (size_t)(rowbase + r) * K + k0 + a_c);
        }
        #pragma unroll
        for (int it = 0; it < 4; it++) {
            const int r = it * 8 + b_r;
            CP_ASYNC16(sb + (uint32_t)(r * B_STRIDE + b_c) * 4,
                       B + (size_t)(k0 + r) * N + colbase + b_c);
        }
        CP_COMMIT();
    };

    load_stage(0, 0);
    load_stage(1, GBK);

    const int arow0 = warpM * 64 + (l >> 2);
    const int bcol0 = warpN * 32 + (l >> 2);
    const int kfrag = (l & 3);

    for (int s = 0; s < S; s++) {
        if (s + 1 < S) { CP_WAIT1(); } else { CP_WAIT0(); }
        __syncthreads();

        const float* as = smem + (s & 1) * STG_FLOATS;
        const float* bs = as + A_FLOATS;
        #pragma unroll
        for (int ks = 0; ks < 4; ks++) {
            const int kk = ks * 8 + kfrag;
            uint32_t af[4][4], bf[4][2];
            #pragma unroll
            for (int i = 0; i < 4; i++) {
                const int r = arow0 + i * 16;
                af[i][0] = __float_as_uint(as[(r    ) * A_STRIDE + kk    ]);
                af[i][1] = __float_as_uint(as[(r + 8) * A_STRIDE + kk    ]);
                af[i][2] = __float_as_uint(as[(r    ) * A_STRIDE + kk + 4]);
                af[i][3] = __float_as_uint(as[(r + 8) * A_STRIDE + kk + 4]);
            }
            #pragma unroll
            for (int j = 0; j < 4; j++) {
                const int n = bcol0 + j * 8;
                bf[j][0] = __float_as_uint(bs[(ks * 8 + kfrag    ) * B_STRIDE + n]);
                bf[j][1] = __float_as_uint(bs[(ks * 8 + kfrag + 4) * B_STRIDE + n]);
            }
            #pragma unroll
            for (int i = 0; i < 4; i++)
                #pragma unroll
                for (int j = 0; j < 4; j++)
                    mma_tf32(acc[i][j], af[i], bf[j]);
        }
        __syncthreads();
        if (s + 2 < S) load_stage(s & 1, (s + 2) * GBK);
    }

    const int erow = rowbase + warpM * 64 + (l >> 2);
    const int ecol = colbase + warpN * 32 + 2 * (l & 3);
    #pragma unroll
    for (int i = 0; i < 4; i++) {
        #pragma unroll
        for (int j = 0; j < 4; j++) {
            const int r0 = erow + i * 16;
            const int c0 = ecol + j * 8;
            const float b0 = bias[c0], b1 = bias[c0 + 1];
            float2 v0, v1;
            if (RND) {
                v0.x = __uint_as_float(f2tf32(acc[i][j][0] + b0));
                v0.y = __uint_as_float(f2tf32(acc[i][j][1] + b1));
                v1.x = __uint_as_float(f2tf32(acc[i][j][2] + b0));
                v1.y = __uint_as_float(f2tf32(acc[i][j][3] + b1));
            } else {
                v0.x = acc[i][j][0] + b0; v0.y = acc[i][j][1] + b1;
                v1.x = acc[i][j][2] + b0; v1.y = acc[i][j][3] + b1;
            }
            *(float2*)(C + (size_t)r0 * N + c0)       = v0;
            *(float2*)(C + (size_t)(r0 + 8) * N + c0) = v1;
        }
    }
}

// ---------------------------------------------------------------------------
// Tensor-core flash attention: single-buffered K/V (cp.async loads),
// 2 CTAs/SM; cross-CTA overlap hides load latency + softmax serial phases.
// CTA = 128 q rows of one (b,h); 8 warps x 16 rows. K-tile = 64 keys.
// ---------------------------------------------------------------------------
#define AQ 128
#define AK 64
#define KS_STRIDE 68
#define VS_STRIDE 72
#define PS_STRIDE 68
#define KS_FLOATS (AK * KS_STRIDE)                 // 4352
#define VS_FLOATS (AK * VS_STRIDE)                 // 4608
#define KV_FLOATS (KS_FLOATS + VS_FLOATS)          // 8960
#define PS_FLOATS (8 * 16 * PS_STRIDE)             // 8704
#define ATTN_SMEM ((KV_FLOATS + PS_FLOATS) * 4)    // 70656 B -> 2 CTAs/SM

__global__ __launch_bounds__(256, 2)
void attn_tc_kernel(const float* __restrict__ qkv, float* __restrict__ out)
{
    extern __shared__ float sm[];
    float* Ksm = sm;
    float* Vsm = sm + KS_FLOATS;
    float* Psm = sm + KV_FLOATS;

    const int qtile = blockIdx.x;
    const int h   = blockIdx.y;
    const int b   = blockIdx.z;
    const int tid = threadIdx.x;
    const int wid = tid >> 5;
    const int l   = tid & 31;
    const int g   = l >> 2;
    const int t   = l & 3;
    const int qb  = qtile * AQ;
    const int rg  = qb + wid * 16 + g;

    const float SC = 0.18033688011112042f;   // (1/sqrt(64)) * log2(e)
    float* Pw = Psm + wid * (16 * PS_STRIDE);
    const uint32_t smb = smem_u32(sm);
    const uint32_t kbuf = smb;
    const uint32_t vbuf = smb + KS_FLOATS * 4;

    // Q fragments (pre-rounded tf32 bits), register-resident
    uint32_t qa[8][4];
    {
        const float* Qr  = qkv + (size_t)(b * SEQ + rg    ) * C3 + h * HDIM;
        const float* Qr8 = qkv + (size_t)(b * SEQ + rg + 8) * C3 + h * HDIM;
        #pragma unroll
        for (int ks = 0; ks < 8; ks++) {
            qa[ks][0] = __float_as_uint(Qr [ks * 8 + t]);
            qa[ks][1] = __float_as_uint(Qr8[ks * 8 + t]);
            qa[ks][2] = __float_as_uint(Qr [ks * 8 + t + 4]);
            qa[ks][3] = __float_as_uint(Qr8[ks * 8 + t + 4]);
        }
    }

    float O[8][4];
    #pragma unroll
    for (int nb = 0; nb < 8; nb++)
        #pragma unroll
        for (int q = 0; q < 4; q++) O[nb][q] = 0.f;
    float m0 = -INFINITY, m1 = -INFINITY, l0 = 0.f, l1 = 0.f;

    const int ntiles = (qb + AQ) / AK;

    for (int ti = 0; ti < ntiles; ti++) {
        const int kb = ti * AK;
        // Load K/V tile (cp.async, 64 x 64 each)
        #pragma unroll
        for (int it = 0; it < 4; it++) {
            const int idx = it * 256 + tid;
            const int r = idx >> 4;
            const int c = (idx & 15) * 4;
            const float* src = qkv + (size_t)(b * SEQ + kb + r) * C3 + h * HDIM + c;
            CP_ASYNC16(kbuf + (uint32_t)(r * KS_STRIDE + c) * 4, src + CDIM);
            CP_ASYNC16(vbuf + (uint32_t)(r * VS_STRIDE + c) * 4, src + 2 * CDIM);
        }
        CP_COMMIT();
        CP_WAIT0();
        __syncthreads();

        // S = Q @ K^T
        float sc[8][4];
        #pragma unroll
        for (int nb = 0; nb < 8; nb++) {
            sc[nb][0] = 0.f; sc[nb][1] = 0.f; sc[nb][2] = 0.f; sc[nb][3] = 0.f;
            #pragma unroll
            for (int ks = 0; ks < 8; ks++) {
                uint32_t bf[2];
                bf[0] = __float_as_uint(Ksm[(nb * 8 + g) * KS_STRIDE + ks * 8 + t    ]);
                bf[1] = __float_as_uint(Ksm[(nb * 8 + g) * KS_STRIDE + ks * 8 + t + 4]);
                mma_tf32(sc[nb], qa[ks], bf);
            }
        }

        float tm0 = -INFINITY, tm1 = -INFINITY;
        #pragma unroll
        for (int nb = 0; nb < 8; nb++) {
            const int k0 = kb + nb * 8 + 2 * t;
            float s0 = sc[nb][0] * SC, s1 = sc[nb][1] * SC;
            float s2 = sc[nb][2] * SC, s3 = sc[nb][3] * SC;
            if (k0     > rg    ) s0 = -INFINITY;
            if (k0 + 1 > rg    ) s1 = -INFINITY;
            if (k0     > rg + 8) s2 = -INFINITY;
            if (k0 + 1 > rg + 8) s3 = -INFINITY;
            sc[nb][0] = s0; sc[nb][1] = s1; sc[nb][2] = s2; sc[nb][3] = s3;
            tm0 = fmaxf(tm0, fmaxf(s0, s1));
            tm1 = fmaxf(tm1, fmaxf(s2, s3));
        }
        tm0 = fmaxf(tm0, __shfl_xor_sync(0xffffffffu, tm0, 1));
        tm0 = fmaxf(tm0, __shfl_xor_sync(0xffffffffu, tm0, 2));
        tm1 = fmaxf(tm1, __shfl_xor_sync(0xffffffffu, tm1, 1));
        tm1 = fmaxf(tm1, __shfl_xor_sync(0xffffffffu, tm1, 2));

        const float nm0 = fmaxf(m0, tm0);
        const float nm1 = fmaxf(m1, tm1);
        const float c0 = fexp2(m0 - nm0);
        const float c1 = fexp2(m1 - nm1);
        l0 *= c0; l1 *= c1;
        #pragma unroll
        for (int nb = 0; nb < 8; nb++) {
            O[nb][0] *= c0; O[nb][1] *= c0;
            O[nb][2] *= c1; O[nb][3] *= c1;
        }
        m0 = nm0; m1 = nm1;

        #pragma unroll
        for (int nb = 0; nb < 8; nb++) {
            float p0 = fexp2(sc[nb][0] - m0);
            float p1 = fexp2(sc[nb][1] - m0);
            float p2 = fexp2(sc[nb][2] - m1);
            float p3 = fexp2(sc[nb][3] - m1);
            l0 += p0 + p1;
            l1 += p2 + p3;
            uint2 u0 = { f2tf32(p0), f2tf32(p1) };
            uint2 u1 = { f2tf32(p2), f2tf32(p3) };
            *(uint2*)(Pw + (g    ) * PS_STRIDE + nb * 8 + 2 * t) = u0;
            *(uint2*)(Pw + (g + 8) * PS_STRIDE + nb * 8 + 2 * t) = u1;
        }
        __syncwarp();

        #pragma unroll
        for (int ks = 0; ks < 8; ks++) {
            uint32_t pa[4];
            pa[0] = __float_as_uint(Pw[(g    ) * PS_STRIDE + ks * 8 + t    ]);
            pa[1] = __float_as_uint(Pw[(g + 8) * PS_STRIDE + ks * 8 + t    ]);
            pa[2] = __float_as_uint(Pw[(g    ) * PS_STRIDE + ks * 8 + t + 4]);
            pa[3] = __float_as_uint(Pw[(g + 8) * PS_STRIDE + ks * 8 + t + 4]);
            #pragma unroll
            for (int nb = 0; nb < 8; nb++) {
                uint32_t bf[2];
                bf[0] = __float_as_uint(Vsm[(ks * 8 + t    ) * VS_STRIDE + nb * 8 + g]);
                bf[1] = __float_as_uint(Vsm[(ks * 8 + t + 4) * VS_STRIDE + nb * 8 + g]);
                mma_tf32(O[nb], pa, bf);
            }
        }
        __syncthreads();   // all warps done with K/V before next tile's load
    }

    l0 += __shfl_xor_sync(0xffffffffu, l0, 1);
    l0 += __shfl_xor_sync(0xffffffffu, l0, 2);
    l1 += __shfl_xor_sync(0xffffffffu, l1, 1);
    l1 += __shfl_xor_sync(0xffffffffu, l1, 2);
    const float inv0 = 1.f / l0;
    const float inv1 = 1.f / l1;

    float* out0 = out + (size_t)(b * SEQ + rg    ) * CDIM + h * HDIM;
    float* out8 = out + (size_t)(b * SEQ + rg + 8) * CDIM + h * HDIM;
    #pragma unroll
    for (int nb = 0; nb < 8; nb++) {
        float2 v0, v1;
        v0.x = __uint_as_float(f2tf32(O[nb][0] * inv0));
        v0.y = __uint_as_float(f2tf32(O[nb][1] * inv0));
        v1.x = __uint_as_float(f2tf32(O[nb][2] * inv1));
        v1.y = __uint_as_float(f2tf32(O[nb][3] * inv1));
        *(float2*)(out0 + nb * 8 + 2 * t) = v0;
        *(float2*)(out8 + nb * 8 + 2 * t) = v1;
    }
}

// ---------------------------------------------------------------------------
// Launch
// ---------------------------------------------------------------------------
extern "C" void kernel_launch(void* const* d_in, const int* in_sizes, int n_in,
                              void* d_out, int out_size)
{
    const float* x    = (const float*)d_in[0];
    const float* Wqkv = (const float*)d_in[1];
    const float* bqkv = (const float*)d_in[2];
    const float* Wout = (const float*)d_in[3];
    const float* bout = (const float*)d_in[4];
    float* out = (float*)d_out;

    float *qkv, *attn, *xr, *wqkvr, *woutr;
    cudaGetSymbolAddress((void**)&qkv,   g_qkv);
    cudaGetSymbolAddress((void**)&attn,  g_attn);
    cudaGetSymbolAddress((void**)&xr,    g_xr);
    cudaGetSymbolAddress((void**)&wqkvr, g_wqkvr);
    cudaGetSymbolAddress((void**)&woutr, g_woutr);

    static bool attr_set = false;
    if (!attr_set) {
        cudaFuncSetAttribute(gemm_tc_kernel<true>,  cudaFuncAttributeMaxDynamicSharedMemorySize, GEMM_SMEM);
        cudaFuncSetAttribute(gemm_tc_kernel<false>, cudaFuncAttributeMaxDynamicSharedMemorySize, GEMM_SMEM);
        cudaFuncSetAttribute(attn_tc_kernel, cudaFuncAttributeMaxDynamicSharedMemorySize, ATTN_SMEM);
        attr_set = true;
    }

    // 0) Pre-round GEMM operands to tf32
    round_tf32_kernel<<<(MROWS * CDIM / 4 + 255) / 256, 256>>>(x,    xr,    MROWS * CDIM / 4);
    round_tf32_kernel<<<(CDIM * C3 / 4 + 255) / 256, 256>>>(Wqkv, wqkvr, CDIM * C3 / 4);
    round_tf32_kernel<<<(CDIM * CDIM / 4 + 255) / 256, 256>>>(Wout, woutr, CDIM * CDIM / 4);

    // 1) QKV projection (rounds outputs -> attention operands pre-rounded)
    {
        dim3 grid(C3 / GBN, MROWS / GBM);
        gemm_tc_kernel<true><<<grid, 256, GEMM_SMEM>>>(xr, wqkvr, bqkv, qkv, MROWS, C3, CDIM);
    }
    // 2) Causal flash attention (tensor cores) -> g_attn (tf32-rounded)
    {
        dim3 grid(SEQ / AQ, NHEAD, BATCH);
        attn_tc_kernel<<<grid, 256, ATTN_SMEM>>>(qkv, attn);
    }
    // 3) Output projection (fp32 output)
    {
        dim3 grid(CDIM / GBN, MROWS / GBM);
        gemm_tc_kernel<false><<<grid, 256, GEMM_SMEM>>>(attn, woutr, bout, out, MROWS, CDIM, CDIM);
    }
}

// round 7
// speedup vs baseline: 1.0602x; 1.0602x over previous
#include <cuda_runtime.h>
#include <cuda_bf16.h>
#include <math.h>
#include <stdint.h>

// Problem constants
#define BATCH 2
#define SEQ   2048
#define CDIM  1024
#define NHEAD 16
#define HDIM  64
#define C3    (3*CDIM)          // 3072
#define MROWS (BATCH*SEQ)       // 4096

// Scratch (no cudaMalloc allowed)
__device__ float g_qkv[(size_t)MROWS * C3];       // [B,T,3,H,D] (tf32-rounded)
__device__ float g_attn[(size_t)MROWS * CDIM];    // [B,T,C]     (tf32-rounded)
__device__ float g_xr[(size_t)MROWS * CDIM];      // x, tf32-rounded
__device__ float g_wqkvr[(size_t)CDIM * C3];      // Wqkv, tf32-rounded
__device__ float g_woutr[(size_t)CDIM * CDIM];    // Wout, tf32-rounded

__device__ __forceinline__ uint32_t f2tf32(float f) {
    uint32_t r;
    asm("cvt.rna.tf32.f32 %0, %1;" : "=r"(r) : "f"(f));
    return r;
}
__device__ __forceinline__ float fexp2(float x) {
    float y;
    asm("ex2.approx.f32 %0, %1;" : "=f"(y) : "f"(x));
    return y;
}
__device__ __forceinline__ uint32_t smem_u32(const void* p) {
    uint32_t a;
    asm("{ .reg .u64 t; cvta.to.shared.u64 t, %1; cvt.u32.u64 %0, t; }" : "=r"(a) : "l"(p));
    return a;
}
#define CP_ASYNC16(dst_u32, src_ptr) \
    asm volatile("cp.async.cg.shared.global [%0], [%1], 16;" :: "r"(dst_u32), "l"(src_ptr) : "memory")
#define CP_COMMIT() asm volatile("cp.async.commit_group;" ::: "memory")
#define CP_WAIT0()  asm volatile("cp.async.wait_group 0;" ::: "memory")
#define CP_WAIT1()  asm volatile("cp.async.wait_group 1;" ::: "memory")
#define CP_WAIT2()  asm volatile("cp.async.wait_group 2;" ::: "memory")

__device__ __forceinline__ void mma_tf32(float c[4], const uint32_t a[4], const uint32_t b[2]) {
    asm volatile(
        "mma.sync.aligned.m16n8k8.row.col.f32.tf32.tf32.f32 "
        "{%0,%1,%2,%3}, {%4,%5,%6,%7}, {%8,%9}, {%0,%1,%2,%3};"
        : "+f"(c[0]), "+f"(c[1]), "+f"(c[2]), "+f"(c[3])
        : "r"(a[0]), "r"(a[1]), "r"(a[2]), "r"(a[3]), "r"(b[0]), "r"(b[1]));
}

// ---------------------------------------------------------------------------
// Fused tf32 pre-round pass over x, Wqkv, Wout (one launch)
// ---------------------------------------------------------------------------
#define RN1 (MROWS * CDIM / 4)
#define RN2 (CDIM * C3 / 4)
#define RN3 (CDIM * CDIM / 4)
#define RNT (RN1 + RN2 + RN3)

__global__ __launch_bounds__(256)
void round3_kernel(const float* __restrict__ x,    float* __restrict__ xr,
                   const float* __restrict__ w1,   float* __restrict__ w1r,
                   const float* __restrict__ w2,   float* __restrict__ w2r)
{
    int i = blockIdx.x * blockDim.x + threadIdx.x;
    const float4* src;
    float4* dst;
    int j;
    if (i < RN1)            { src = (const float4*)x;  dst = (float4*)xr;  j = i; }
    else if (i < RN1 + RN2) { src = (const float4*)w1; dst = (float4*)w1r; j = i - RN1; }
    else if (i < RNT)       { src = (const float4*)w2; dst = (float4*)w2r; j = i - RN1 - RN2; }
    else return;
    float4 v = src[j];
    float4 o;
    o.x = __uint_as_float(f2tf32(v.x));
    o.y = __uint_as_float(f2tf32(v.y));
    o.z = __uint_as_float(f2tf32(v.z));
    o.w = __uint_as_float(f2tf32(v.w));
    dst[j] = o;
}

// ---------------------------------------------------------------------------
// tf32 mma.sync GEMM + bias, cp.async 3-stage pipeline (R5 structure).
// C[M,N] = A[M,K] @ B[K,N] + bias[N]. A,B must be tf32-pre-rounded.
// CTA 128x128, BK=32, 8 warps (2x4), warp tile 64x32.
// ---------------------------------------------------------------------------
#define GBM 128
#define GBN 128
#define GBK 32
#define A_STRIDE 36
#define B_STRIDE 136
#define A_FLOATS (GBM * A_STRIDE)       // 4608
#define B_FLOATS (GBK * B_STRIDE)       // 4352
#define STG_FLOATS (A_FLOATS + B_FLOATS)
#define GEMM_SMEM (3 * STG_FLOATS * 4)  // 107520 B

template<bool RND>
__global__ __launch_bounds__(256)
void gemm_tc_kernel(const float* __restrict__ A,
                    const float* __restrict__ B,
                    const float* __restrict__ bias,
                    float* __restrict__ C,
                    int M, int N, int K)
{
    extern __shared__ float smem[];
    const int tid = threadIdx.x;
    const int wid = tid >> 5;
    const int l   = tid & 31;
    const int warpM = wid >> 2;
    const int warpN = wid & 3;
    const int rowbase = blockIdx.y * GBM;
    const int colbase = blockIdx.x * GBN;

    const uint32_t smb = smem_u32(smem);

    float acc[4][4][4];
    #pragma unroll
    for (int i = 0; i < 4; i++)
        #pragma unroll
        for (int j = 0; j < 4; j++)
            #pragma unroll
            for (int q = 0; q < 4; q++) acc[i][j][q] = 0.f;

    const int a_r = tid >> 3, a_c = (tid & 7) * 4;
    const int b_r = tid >> 5, b_c = (tid & 31) * 4;

    const int S = K / GBK;

    auto load_stage = [&](int stg, int k0) {
        const uint32_t sa = smb + stg * STG_FLOATS * 4;
        const uint32_t sb = sa + A_FLOATS * 4;
        #pragma unroll
        for (int it = 0; it < 4; it++) {
            const int r = it * 32 + a_r;
            CP_ASYNC16(sa + (uint32_t)(r * A_STRIDE + a_c) * 4,
                       A + (size_t)(rowbase + r) * K + k0 + a_c);
        }
        #pragma unroll
        for (int it = 0; it < 4; it++) {
            const int r = it * 8 + b_r;
            CP_ASYNC16(sb + (uint32_t)(r * B_STRIDE + b_c) * 4,
                       B + (size_t)(k0 + r) * N + colbase + b_c);
        }
        CP_COMMIT();
    };

    load_stage(0, 0);
    load_stage(1, GBK);

    const int arow0 = warpM * 64 + (l >> 2);
    const int bcol0 = warpN * 32 + (l >> 2);
    const int kfrag = (l & 3);

    for (int s = 0; s < S; s++) {
        if (s + 2 < S) { load_stage((s + 2) % 3, (s + 2) * GBK); CP_WAIT2(); }
        else if (s + 1 < S) { CP_WAIT1(); }
        else { CP_WAIT0(); }
        __syncthreads();

        const float* as = smem + (s % 3) * STG_FLOATS;
        const float* bs = as + A_FLOATS;
        #pragma unroll
        for (int ks = 0; ks < 4; ks++) {
            const int kk = ks * 8 + kfrag;
            uint32_t af[4][4], bf[4][2];
            #pragma unroll
            for (int i = 0; i < 4; i++) {
                const int r = arow0 + i * 16;
                af[i][0] = __float_as_uint(as[(r    ) * A_STRIDE + kk    ]);
                af[i][1] = __float_as_uint(as[(r + 8) * A_STRIDE + kk    ]);
                af[i][2] = __float_as_uint(as[(r    ) * A_STRIDE + kk + 4]);
                af[i][3] = __float_as_uint(as[(r + 8) * A_STRIDE + kk + 4]);
            }
            #pragma unroll
            for (int j = 0; j < 4; j++) {
                const int n = bcol0 + j * 8;
                bf[j][0] = __float_as_uint(bs[(ks * 8 + kfrag    ) * B_STRIDE + n]);
                bf[j][1] = __float_as_uint(bs[(ks * 8 + kfrag + 4) * B_STRIDE + n]);
            }
            #pragma unroll
            for (int i = 0; i < 4; i++)
                #pragma unroll
                for (int j = 0; j < 4; j++)
                    mma_tf32(acc[i][j], af[i], bf[j]);
        }
        __syncthreads();
    }

    const int erow = rowbase + warpM * 64 + (l >> 2);
    const int ecol = colbase + warpN * 32 + 2 * (l & 3);
    #pragma unroll
    for (int i = 0; i < 4; i++) {
        #pragma unroll
        for (int j = 0; j < 4; j++) {
            const int r0 = erow + i * 16;
            const int c0 = ecol + j * 8;
            const float b0 = bias[c0], b1 = bias[c0 + 1];
            float2 v0, v1;
            if (RND) {
                v0.x = __uint_as_float(f2tf32(acc[i][j][0] + b0));
                v0.y = __uint_as_float(f2tf32(acc[i][j][1] + b1));
                v1.x = __uint_as_float(f2tf32(acc[i][j][2] + b0));
                v1.y = __uint_as_float(f2tf32(acc[i][j][3] + b1));
            } else {
                v0.x = acc[i][j][0] + b0; v0.y = acc[i][j][1] + b1;
                v1.x = acc[i][j][2] + b0; v1.y = acc[i][j][3] + b1;
            }
            *(float2*)(C + (size_t)r0 * N + c0)       = v0;
            *(float2*)(C + (size_t)(r0 + 8) * N + c0) = v1;
        }
    }
}

// ---------------------------------------------------------------------------
// Tensor-core flash attention: cp.async double-buffered K/V (R5 structure)
// + scale folded into Q fragments + warp-uniform causal-mask skip.
// CTA = 128 q rows of one (b,h); 8 warps x 16 rows. K-tile = 64 keys.
// ---------------------------------------------------------------------------
#define AQ 128
#define AK 64
#define KS_STRIDE 68
#define VS_STRIDE 72
#define PS_STRIDE 68
#define KS_FLOATS (AK * KS_STRIDE)                 // 4352
#define VS_FLOATS (AK * VS_STRIDE)                 // 4608
#define KV_FLOATS (KS_FLOATS + VS_FLOATS)          // 8960 per stage
#define PS_FLOATS (8 * 16 * PS_STRIDE)             // 8704
#define ATTN_SMEM ((2 * KV_FLOATS + PS_FLOATS) * 4) // 106496 B

__global__ __launch_bounds__(256)
void attn_tc_kernel(const float* __restrict__ qkv, float* __restrict__ out)
{
    extern __shared__ float sm[];
    float* Psm = sm + 2 * KV_FLOATS;

    const int qtile = blockIdx.x;
    const int h   = blockIdx.y;
    const int b   = blockIdx.z;
    const int tid = threadIdx.x;
    const int wid = tid >> 5;
    const int l   = tid & 31;
    const int g   = l >> 2;
    const int t   = l & 3;
    const int qb  = qtile * AQ;
    const int rg  = qb + wid * 16 + g;

    const float SC = 0.18033688011112042f;   // (1/sqrt(64)) * log2(e)
    float* Pw = Psm + wid * (16 * PS_STRIDE);
    const uint32_t smb = smem_u32(sm);

    auto load_kv = [&](int stg, int kb) {
        const uint32_t kbuf = smb + stg * KV_FLOATS * 4;
        const uint32_t vbuf = kbuf + KS_FLOATS * 4;
        #pragma unroll
        for (int it = 0; it < 4; it++) {
            const int idx = it * 256 + tid;
            const int r = idx >> 4;
            const int c = (idx & 15) * 4;
            const float* src = qkv + (size_t)(b * SEQ + kb + r) * C3 + h * HDIM + c;
            CP_ASYNC16(kbuf + (uint32_t)(r * KS_STRIDE + c) * 4, src + CDIM);
            CP_ASYNC16(vbuf + (uint32_t)(r * VS_STRIDE + c) * 4, src + 2 * CDIM);
        }
        CP_COMMIT();
    };

    // Q fragments with softmax scale pre-folded (tf32-rounded)
    uint32_t qa[8][4];
    {
        const float* Qr  = qkv + (size_t)(b * SEQ + rg    ) * C3 + h * HDIM;
        const float* Qr8 = qkv + (size_t)(b * SEQ + rg + 8) * C3 + h * HDIM;
        #pragma unroll
        for (int ks = 0; ks < 8; ks++) {
            qa[ks][0] = f2tf32(Qr [ks * 8 + t]     * SC);
            qa[ks][1] = f2tf32(Qr8[ks * 8 + t]     * SC);
            qa[ks][2] = f2tf32(Qr [ks * 8 + t + 4] * SC);
            qa[ks][3] = f2tf32(Qr8[ks * 8 + t + 4] * SC);
        }
    }

    float O[8][4];
    #pragma unroll
    for (int nb = 0; nb < 8; nb++)
        #pragma unroll
        for (int q = 0; q < 4; q++) O[nb][q] = 0.f;
    float m0 = -INFINITY, m1 = -INFINITY, l0 = 0.f, l1 = 0.f;

    const int ntiles = (qb + AQ) / AK;

    load_kv(0, 0);

    for (int ti = 0; ti < ntiles; ti++) {
        if (ti + 1 < ntiles) { load_kv((ti + 1) & 1, (ti + 1) * AK); CP_WAIT1(); }
        else { CP_WAIT0(); }
        __syncthreads();

        const float* Ksm = sm + (ti & 1) * KV_FLOATS;
        const float* Vsm = Ksm + KS_FLOATS;
        const int kb = ti * AK;

        // S = Q @ K^T (already scaled, log2 domain)
        float sc[8][4];
        #pragma unroll
        for (int nb = 0; nb < 8; nb++) {
            sc[nb][0] = 0.f; sc[nb][1] = 0.f; sc[nb][2] = 0.f; sc[nb][3] = 0.f;
            #pragma unroll
            for (int ks = 0; ks < 8; ks++) {
                uint32_t bf[2];
                bf[0] = __float_as_uint(Ksm[(nb * 8 + g) * KS_STRIDE + ks * 8 + t    ]);
                bf[1] = __float_as_uint(Ksm[(nb * 8 + g) * KS_STRIDE + ks * 8 + t + 4]);
                mma_tf32(sc[nb], qa[ks], bf);
            }
        }

        // Causal mask only needed on tiles overlapping this warp's diagonal
        const bool needmask = (kb + AK - 1) > (qb + wid * 16);
        float tm0 = -INFINITY, tm1 = -INFINITY;
        if (needmask) {
            #pragma unroll
            for (int nb = 0; nb < 8; nb++) {
                const int k0 = kb + nb * 8 + 2 * t;
                if (k0     > rg    ) sc[nb][0] = -INFINITY;
                if (k0 + 1 > rg    ) sc[nb][1] = -INFINITY;
                if (k0     > rg + 8) sc[nb][2] = -INFINITY;
                if (k0 + 1 > rg + 8) sc[nb][3] = -INFINITY;
                tm0 = fmaxf(tm0, fmaxf(sc[nb][0], sc[nb][1]));
                tm1 = fmaxf(tm1, fmaxf(sc[nb][2], sc[nb][3]));
            }
        } else {
            #pragma unroll
            for (int nb = 0; nb < 8; nb++) {
                tm0 = fmaxf(tm0, fmaxf(sc[nb][0], sc[nb][1]));
                tm1 = fmaxf(tm1, fmaxf(sc[nb][2], sc[nb][3]));
            }
        }
        tm0 = fmaxf(tm0, __shfl_xor_sync(0xffffffffu, tm0, 1));
        tm0 = fmaxf(tm0, __shfl_xor_sync(0xffffffffu, tm0, 2));
        tm1 = fmaxf(tm1, __shfl_xor_sync(0xffffffffu, tm1, 1));
        tm1 = fmaxf(tm1, __shfl_xor_sync(0xffffffffu, tm1, 2));

        const float nm0 = fmaxf(m0, tm0);
        const float nm1 = fmaxf(m1, tm1);
        const float c0 = fexp2(m0 - nm0);
        const float c1 = fexp2(m1 - nm1);
        l0 *= c0; l1 *= c1;
        #pragma unroll
        for (int nb = 0; nb < 8; nb++) {
            O[nb][0] *= c0; O[nb][1] *= c0;
            O[nb][2] *= c1; O[nb][3] *= c1;
        }
        m0 = nm0; m1 = nm1;

        #pragma unroll
        for (int nb = 0; nb < 8; nb++) {
            float p0 = fexp2(sc[nb][0] - m0);
            float p1 = fexp2(sc[nb][1] - m0);
            float p2 = fexp2(sc[nb][2] - m1);
            float p3 = fexp2(sc[nb][3] - m1);
            l0 += p0 + p1;
            l1 += p2 + p3;
            uint2 u0 = { f2tf32(p0), f2tf32(p1) };
            uint2 u1 = { f2tf32(p2), f2tf32(p3) };
            *(uint2*)(Pw + (g    ) * PS_STRIDE + nb * 8 + 2 * t) = u0;
            *(uint2*)(Pw + (g + 8) * PS_STRIDE + nb * 8 + 2 * t) = u1;
        }
        __syncwarp();

        #pragma unroll
        for (int ks = 0; ks < 8; ks++) {
            uint32_t pa[4];
            pa[0] = __float_as_uint(Pw[(g    ) * PS_STRIDE + ks * 8 + t    ]);
            pa[1] = __float_as_uint(Pw[(g + 8) * PS_STRIDE + ks * 8 + t    ]);
            pa[2] = __float_as_uint(Pw[(g    ) * PS_STRIDE + ks * 8 + t + 4]);
            pa[3] = __float_as_uint(Pw[(g + 8) * PS_STRIDE + ks * 8 + t + 4]);
            #pragma unroll
            for (int nb = 0; nb < 8; nb++) {
                uint32_t bf[2];
                bf[0] = __float_as_uint(Vsm[(ks * 8 + t    ) * VS_STRIDE + nb * 8 + g]);
                bf[1] = __float_as_uint(Vsm[(ks * 8 + t + 4) * VS_STRIDE + nb * 8 + g]);
                mma_tf32(O[nb], pa, bf);
            }
        }
        __syncthreads();   // all warps done with this K/V buffer before reload
    }

    l0 += __shfl_xor_sync(0xffffffffu, l0, 1);
    l0 += __shfl_xor_sync(0xffffffffu, l0, 2);
    l1 += __shfl_xor_sync(0xffffffffu, l1, 1);
    l1 += __shfl_xor_sync(0xffffffffu, l1, 2);
    const float inv0 = 1.f / l0;
    const float inv1 = 1.f / l1;

    float* out0 = out + (size_t)(b * SEQ + rg    ) * CDIM + h * HDIM;
    float* out8 = out + (size_t)(b * SEQ + rg + 8) * CDIM + h * HDIM;
    #pragma unroll
    for (int nb = 0; nb < 8; nb++) {
        float2 v0, v1;
        v0.x = __uint_as_float(f2tf32(O[nb][0] * inv0));
        v0.y = __uint_as_float(f2tf32(O[nb][1] * inv0));
        v1.x = __uint_as_float(f2tf32(O[nb][2] * inv1));
        v1.y = __uint_as_float(f2tf32(O[nb][3] * inv1));
        *(float2*)(out0 + nb * 8 + 2 * t) = v0;
        *(float2*)(out8 + nb * 8 + 2 * t) = v1;
    }
}

// ---------------------------------------------------------------------------
// Launch
// ---------------------------------------------------------------------------
extern "C" void kernel_launch(void* const* d_in, const int* in_sizes, int n_in,
                              void* d_out, int out_size)
{
    const float* x    = (const float*)d_in[0];
    const float* Wqkv = (const float*)d_in[1];
    const float* bqkv = (const float*)d_in[2];
    const float* Wout = (const float*)d_in[3];
    const float* bout = (const float*)d_in[4];
    float* out = (float*)d_out;

    float *qkv, *attn, *xr, *wqkvr, *woutr;
    cudaGetSymbolAddress((void**)&qkv,   g_qkv);
    cudaGetSymbolAddress((void**)&attn,  g_attn);
    cudaGetSymbolAddress((void**)&xr,    g_xr);
    cudaGetSymbolAddress((void**)&wqkvr, g_wqkvr);
    cudaGetSymbolAddress((void**)&woutr, g_woutr);

    static bool attr_set = false;
    if (!attr_set) {
        cudaFuncSetAttribute(gemm_tc_kernel<true>,  cudaFuncAttributeMaxDynamicSharedMemorySize, GEMM_SMEM);
        cudaFuncSetAttribute(gemm_tc_kernel<false>, cudaFuncAttributeMaxDynamicSharedMemorySize, GEMM_SMEM);
        cudaFuncSetAttribute(attn_tc_kernel, cudaFuncAttributeMaxDynamicSharedMemorySize, ATTN_SMEM);
        attr_set = true;
    }

    // 0) Pre-round GEMM operands to tf32 (single fused launch)
    round3_kernel<<<(RNT + 255) / 256, 256>>>(x, xr, Wqkv, wqkvr, Wout, woutr);

    // 1) QKV projection (rounds outputs -> attention operands pre-rounded)
    {
        dim3 grid(C3 / GBN, MROWS / GBM);
        gemm_tc_kernel<true><<<grid, 256, GEMM_SMEM>>>(xr, wqkvr, bqkv, qkv, MROWS, C3, CDIM);
    }
    // 2) Causal flash attention (tensor cores) -> g_attn (tf32-rounded)
    {
        dim3 grid(SEQ / AQ, NHEAD, BATCH);
        attn_tc_kernel<<<grid, 256, ATTN_SMEM>>>(qkv, attn);
    }
    // 3) Output projection (fp32 output)
    {
        dim3 grid(CDIM / GBN, MROWS / GBM);
        gemm_tc_kernel<false><<<grid, 256, GEMM_SMEM>>>(attn, woutr, bout, out, MROWS, CDIM, CDIM);
    }
}